// round 10
// baseline (speedup 1.0000x reference)
#include <cuda_runtime.h>
#include <cuda_bf16.h>

#define NN 320
#define DD 256
#define GB 101   // grid size: <= 148 SMs -> all blocks resident -> safe spin barriers

// Scratch (allocation-free device globals), 128B-aligned to avoid cross-SM
// L1 false sharing on same-launch reads.
__device__ __align__(128) float  g_L[NN * NN];       // logits
__device__ __align__(128) float  g_E[NN * NN];       // exp(logits)
__device__ __align__(128) float  g_ys[NN];           // sorted y_times
__device__ __align__(128) int    g_perm[NN];         // sorted pos -> original idx
__device__ __align__(128) int    g_se[NN];           // event class, sorted order
__device__ __align__(128) int    g_gt[NN];           // per k: count !(ys-yk > 0)
__device__ __align__(128) int    g_geq[NN];          // per k: count (ys-yk < 0)
__device__ __align__(128) float2 g_P[NN * (NN + 1)]; // per-row class-split E prefix
__device__ __align__(128) int    g_cnt[NN + 32];     // class-count prefix (padded)
__device__ __align__(128) float  g_loss[NN];
__device__ __align__(128) float  g_pos[NN];
__device__ __align__(128) int    g_bar1;             // grid barrier 1 (monotone)
__device__ __align__(128) int    g_bar2;             // grid barrier 2 (monotone)
__device__ __align__(128) int    g_ctr;              // lossk completion (monotone)

// TABLE rows packed: weight code c in {0,1,2} (weight = c*0.5) at bits [2v+1:2v],
// v = td + 3*e, td in {1(lower),2(middle),3(upper)}.
__constant__ int c_rb[7] = {8852, 5460, 4692, 5460, 5716, 4436, 8852};

typedef unsigned long long ull;

// Packed fp32x2 helpers (sm_103a FFMA2 path). acc += (x + ny)^2 pairwise;
// x + (-y) is IEEE-identical to x - y.
__device__ __forceinline__ void dsq_acc(ull& acc, ull x, ull ny) {
    ull d;
    asm("add.rn.f32x2 %0, %1, %2;" : "=l"(d) : "l"(x), "l"(ny));
    asm("fma.rn.f32x2 %0, %1, %1, %0;" : "+l"(acc) : "l"(d));
}
__device__ __forceinline__ float dsum(ull acc) {
    unsigned lo, hi;
    asm("mov.b64 {%0, %1}, %2;" : "=r"(lo), "=r"(hi) : "l"(acc));
    return __uint_as_float(lo) + __uint_as_float(hi);
}

// Grid barrier: all GB blocks resident (grid <= #SMs) -> spin is safe.
// Monotone counter: epoch = old/GB, works across graph replays with no reset.
__device__ __forceinline__ void grid_barrier(int* bar, int t) {
    __threadfence();
    __syncthreads();
    if (t == 0) {
        int old = atomicAdd(bar, 1);
        int target = (old / GB + 1) * GB;
        while (atomicAdd(bar, 0) < target) __nanosleep(64);
    }
    __syncthreads();
}

// ---------------------------------------------------------------------------
// ONE kernel, three phases separated by software grid barriers.
// Phase 0: blocks 0..99 = 32x32 distance tiles (R4-proven structure: d-major
//          float2 smem, FFMA2 subtract-form, 2 K-stages; diag accumulates
//          exactly +0, matching the reference's no-op row-max). Block 100 =
//          exact rank sort + run bounds.
// Phase A: class-split E prefix sums per row (blocks stripe rows by GB).
// Phase B: per-anchor loss via 2 binary searches + prefix assembly; exact
//          integer-count validity; final scalar by the 320th finisher.
// ---------------------------------------------------------------------------
__global__ void __launch_bounds__(320)
mega_kernel(const float* __restrict__ F,
            const float* __restrict__ yt,
            const int* __restrict__ ye,
            float* __restrict__ out) {
    __shared__ float2 sA[64][33];   // d-major A tile (per 128-K stage)
    __shared__ float2 sB[64][33];   // negated B tile
    __shared__ float  s_y[NN];
    __shared__ float  ws0[10], ws1[10], wo0[10], wo1[10];
    __shared__ int    wsi[10], woi[10];
    __shared__ float  s_ys[NN];
    __shared__ int    s_cnt[NN + 1];
    __shared__ int    s_rb[7];
    __shared__ float  rS[10], rC[10];
    __shared__ int    s_last;

    int b = blockIdx.x;
    int t = threadIdx.x;          // 0..319
    int lane = t & 31, w = t >> 5;

    // ======================= Phase 0: distances + sort =====================
    if (b < 100) {
        bool act = (t < 256);
        int row = t >> 3;             // 0..31 (for t<256)
        int cg = (t & 7) << 4;        // 0,16,...,112 floats within 128-K stage
        int tx = t & 15, ty = (t >> 4) & 15;
        int bi = (b / 10) * 32, bj = (b % 10) * 32;
        ull a00 = 0ull, a01 = 0ull, a10 = 0ull, a11 = 0ull;

        for (int s = 0; s < 2; s++) {
            if (act) {
                const float* pA = F + (bi + row) * DD + s * 128 + cg;
                const float* pB = F + (bj + row) * DD + s * 128 + cg;
#pragma unroll
                for (int q = 0; q < 4; q++) {
                    float4 av = *(const float4*)(pA + 4 * q);
                    float4 bv = *(const float4*)(pB + 4 * q);
                    int dp = (cg + 4 * q) >> 1;
                    sA[dp][row]     = make_float2(av.x, av.y);
                    sA[dp + 1][row] = make_float2(av.z, av.w);
                    sB[dp][row]     = make_float2(-bv.x, -bv.y);
                    sB[dp + 1][row] = make_float2(-bv.z, -bv.w);
                }
            }
            __syncthreads();
            if (act) {
#pragma unroll 16
                for (int dd = 0; dd < 64; dd++) {
                    ull x0 = *(const ull*)&sA[dd][2 * ty];
                    ull x1 = *(const ull*)&sA[dd][2 * ty + 1];
                    ull y0 = *(const ull*)&sB[dd][2 * tx];
                    ull y1 = *(const ull*)&sB[dd][2 * tx + 1];
                    dsq_acc(a00, x0, y0);
                    dsq_acc(a01, x0, y1);
                    dsq_acc(a10, x1, y0);
                    dsq_acc(a11, x1, y1);
                }
            }
            __syncthreads();
        }
        if (act) {
            int i0 = bi + 2 * ty, j0 = bj + 2 * tx;
            float L;
            L = -0.5f * sqrtf(dsum(a00)); g_L[i0 * NN + j0]           = L; g_E[i0 * NN + j0]           = __expf(L);
            L = -0.5f * sqrtf(dsum(a01)); g_L[i0 * NN + j0 + 1]       = L; g_E[i0 * NN + j0 + 1]       = __expf(L);
            L = -0.5f * sqrtf(dsum(a10)); g_L[(i0 + 1) * NN + j0]     = L; g_E[(i0 + 1) * NN + j0]     = __expf(L);
            L = -0.5f * sqrtf(dsum(a11)); g_L[(i0 + 1) * NN + j0 + 1] = L; g_E[(i0 + 1) * NN + j0 + 1] = __expf(L);
        }
    } else {  // b == 100: exact rank sort + run bounds, one anchor per thread
        s_y[t] = yt[t];
        __syncthreads();
        {
            int e = t;
            float v = s_y[e];
            int rank = 0, gt = 0, geq = 0;
#pragma unroll 8
            for (int j = 0; j < NN; j++) {
                float wv = s_y[j];
                float d = wv - v;                        // same float expr as reference pld
                rank += (wv < v) || (wv == v && j < e);  // unique tie-broken rank
                gt  += !(d > 0.0f);
                geq += (d < 0.0f);
            }
            g_ys[rank] = v; g_perm[rank] = e; g_se[rank] = __ldg(&ye[e]);
            g_gt[e] = gt; g_geq[e] = geq;
        }
    }

    grid_barrier(&g_bar1, t);

    // ================= Phase A: class-split prefix sums (scan) =============
    for (int i = b; i < NN; i += GB) {
        int pj = g_perm[t];
        int cls = g_se[t];
        float Ev = (pj == i) ? 0.f : __ldg(&g_E[i * NN + pj]);   // eye mask folded
        float x0 = cls ? 0.f : Ev;
        float x1 = cls ? Ev : 0.f;
        int   xc = cls ? (1 << 10) : 1;

#pragma unroll
        for (int off = 1; off < 32; off <<= 1) {
            float a0 = __shfl_up_sync(0xffffffffu, x0, off);
            float a1 = __shfl_up_sync(0xffffffffu, x1, off);
            int   ac = __shfl_up_sync(0xffffffffu, xc, off);
            if (lane >= off) { x0 += a0; x1 += a1; xc += ac; }
        }
        if (lane == 31) { ws0[w] = x0; ws1[w] = x1; wsi[w] = xc; }
        __syncthreads();
        if (t == 0) {
            float r0 = 0.f, r1 = 0.f; int ri = 0;
#pragma unroll
            for (int q = 0; q < 10; q++) {
                wo0[q] = r0; wo1[q] = r1; woi[q] = ri;
                r0 += ws0[q]; r1 += ws1[q]; ri += wsi[q];
            }
        }
        __syncthreads();
        x0 += wo0[w]; x1 += wo1[w];
        float2* Prow = g_P + i * (NN + 1);
        Prow[t + 1] = make_float2(x0, x1);
        if (t == 0) Prow[0] = make_float2(0.f, 0.f);
        if (i == 0) {
            g_cnt[t + 1] = xc + woi[w];
            if (t == 0) g_cnt[0] = 0;
        }
        __syncthreads();   // ws/wo reused next iteration
    }

    grid_barrier(&g_bar2, t);

    // ======================= Phase B: per-anchor loss =======================
    s_ys[t] = g_ys[t];
    s_cnt[t] = __ldcg(&g_cnt[t]);
    if (t == 0) s_cnt[NN] = __ldcg(&g_cnt[NN]);
    if (t < 7) s_rb[t] = c_rb[t];
    __syncthreads();

    int   i  = t;
    float yi = yt[i];
    int   ei = ye[i];
    const float2* Prow = g_P + i * (NN + 1);

    for (int k = b; k < NN; k += GB) {
        float yk = __ldg(&yt[k]);
        int   ek = __ldg(&ye[k]);
        int   gt = g_gt[k], geq = g_geq[k];

        float pi = yi - yk;
        float a = fabsf(pi), na = -a;

        int base = ei + 10 * ek;
        int cid = (pi > 0.f) ? base : ((pi < 0.f) ? -base : 0);
        int cidx = (cid == -11) ? 0 : (cid == -10) ? 1 : (cid == -1) ? 2 :
                   (cid == 0)   ? 3 : (cid == 1)   ? 4 : (cid == 10) ? 5 : 6;
        int rb = s_rb[cidx];

        // hi: first m with ys[m]-yk > a  (identical float expr as reference)
        int first = 0, count = NN;
        while (count > 0) {
            int half = count >> 1, mid = first + half;
            if (!(s_ys[mid] - yk > a)) { first = mid + 1; count -= half + 1; }
            else count = half;
        }
        int hi = first;
        // lo: first m with !(ys[m]-yk < -a)
        first = 0; count = NN;
        while (count > 0) {
            int half = count >> 1, mid = first + half;
            if (s_ys[mid] - yk < na) { first = mid + 1; count -= half + 1; }
            else count = half;
        }
        int lo = first;

        // __ldcg: g_P rows are not 128B-line aligned; avoid L1 false sharing.
        float2 Pend = __ldcg(&Prow[NN]);
        float2 Phi  = __ldcg(&Prow[hi]);
        float2 Plo  = __ldcg(&Prow[lo]);
        float2 Pgt  = __ldcg(&Prow[gt]);
        float2 Pgq  = __ldcg(&Prow[geq]);
        float SU0 = Pend.x - Phi.x, SU1 = Pend.y - Phi.y;
        float SL0 = Plo.x,          SL1 = Plo.y;
        float SM0 = (Phi.x - Plo.x) - (Pgt.x - Pgq.x);
        float SM1 = (Phi.y - Plo.y) - (Pgt.y - Pgq.y);

        float w10 = (float)((rb >> 2)  & 3), w20 = (float)((rb >> 4)  & 3), w30 = (float)((rb >> 6)  & 3);
        float w11 = (float)((rb >> 8)  & 3), w21 = (float)((rb >> 10) & 3), w31 = (float)((rb >> 12) & 3);
        float denom = 0.5f * (w10 * SL0 + w11 * SL1 + w20 * SM0 + w21 * SM1 + w30 * SU0 + w31 * SU1);

        // Exact integer validity: counts of positive-weight elements.
        int cU = s_cnt[NN] - s_cnt[hi];
        int cL = s_cnt[lo];
        int cM = (s_cnt[hi] - s_cnt[lo]) - (s_cnt[gt] - s_cnt[geq]);
        if (pi != 0.f) cM -= (ei ? (1 << 10) : 1);   // i sits in middle, weight 0 (eye)
        int nz = rb | (rb >> 1);
        int vsum = ((nz >> 2) & 1) * (cL & 1023) + ((nz >> 8)  & 1) * (cL >> 10)
                 + ((nz >> 4) & 1) * (cM & 1023) + ((nz >> 10) & 1) * (cM >> 10)
                 + ((nz >> 6) & 1) * (cU & 1023) + ((nz >> 12) & 1) * (cU >> 10);
        bool valid = (vsum > 0) && (i != k);

        float res = valid ? (__ldg(&g_L[k * NN + i]) - __logf(denom)) : 0.f;  // L symmetric
        float c   = valid ? 1.f : 0.f;

#pragma unroll
        for (int sh = 16; sh > 0; sh >>= 1) {
            res += __shfl_xor_sync(0xffffffffu, res, sh);
            c   += __shfl_xor_sync(0xffffffffu, c,   sh);
        }
        if (lane == 0) { rS[w] = res; rC[w] = c; }
        __syncthreads();
        if (t == 0) {
            float S = 0.f, C = 0.f;
#pragma unroll
            for (int q = 0; q < 10; q++) { S += rS[q]; C += rC[q]; }
            g_loss[k] = (C > 0.f) ? (-S / C) : 0.f;
            g_pos[k]  = (C > 0.f) ? 1.f : 0.f;
            __threadfence();
            int old = atomicAdd(&g_ctr, 1);
            s_last = ((old % NN) == NN - 1);   // monotone: no reset across replays
        }
        __syncthreads();
        if (s_last) {
            float sa = __ldcg(&g_loss[t]), sb = __ldcg(&g_pos[t]);
#pragma unroll
            for (int sh = 16; sh > 0; sh >>= 1) {
                sa += __shfl_xor_sync(0xffffffffu, sa, sh);
                sb += __shfl_xor_sync(0xffffffffu, sb, sh);
            }
            if (lane == 0) { rS[w] = sa; rC[w] = sb; }
            __syncthreads();
            if (t == 0) {
                float S = 0.f, P = 0.f;
#pragma unroll
                for (int q = 0; q < 10; q++) { S += rS[q]; P += rC[q]; }
                out[0] = S / P;
            }
        }
        __syncthreads();   // rS/rC/s_last reused next iteration
    }
}

extern "C" void kernel_launch(void* const* d_in, const int* in_sizes, int n_in,
                              void* d_out, int out_size) {
    const float* features = (const float*)d_in[0];   // [320, 256] f32
    const float* y_times  = (const float*)d_in[1];   // [320] f32
    const int*   y_events = (const int*)d_in[2];     // [320] i32
    float* out = (float*)d_out;

    mega_kernel<<<GB, 320>>>(features, y_times, y_events, out);
}

// round 11
// speedup vs baseline: 1.2089x; 1.2089x over previous
#include <cuda_runtime.h>
#include <cuda_bf16.h>

#define NN 320
#define DD 256
#define TS 16            // tile size
#define NTB (20 * 20)    // 400 tile blocks

// Scratch (allocation-free device globals)
__device__ float  g_L[NN * NN];       // logits (bit-exact symmetric)
__device__ float  g_E[NN * NN];       // exp(logits)
__device__ float  g_ys[NN];           // sorted y_times
__device__ int    g_perm[NN];         // sorted pos -> original index
__device__ int    g_se[NN];           // event class in sorted order
__device__ int    g_gt[NN];           // per k: count of !(ys-yk > 0)
__device__ int    g_geq[NN];          // per k: count of (ys-yk < 0)
__device__ float2 g_P[NN * (NN + 1)]; // per-row class-split E prefix sums
__device__ int    g_cnt[NN + 1];      // class-count prefix, packed c1<<10 | c0
__device__ float  g_loss[NN];
__device__ float  g_pos[NN];
__device__ int    g_ctr;              // lossk completion (monotone across replays)

// TABLE rows packed: weight code c in {0,1,2} (weight = c*0.5) at bits [2v+1:2v],
// v = td + 3*e, td in {1(lower),2(middle),3(upper)}.
__constant__ int c_rb[7] = {8852, 5460, 4692, 5460, 5716, 4436, 8852};

typedef unsigned long long ull;

// Packed fp32x2 helpers (sm_103a FFMA2 path — only reachable via PTX).
// acc += (x + ny)^2 elementwise; x + (-y) is IEEE-identical to x - y.
__device__ __forceinline__ void dsq_acc(ull& acc, ull x, ull ny) {
    ull d;
    asm("add.rn.f32x2 %0, %1, %2;" : "=l"(d) : "l"(x), "l"(ny));
    asm("fma.rn.f32x2 %0, %1, %1, %0;" : "+l"(acc) : "l"(d));
}
__device__ __forceinline__ float dsum(ull acc) {
    unsigned lo, hi;
    asm("mov.b64 {%0, %1}, %2;" : "=r"(lo), "=r"(hi) : "l"(acc));
    return __uint_as_float(lo) + __uint_as_float(hi);
}

#define RSTRIDE 130    // float2 per smem row: 16B-aligned, bank-pair step 4/row

// ---------------------------------------------------------------------------
// Kernel 1: blocks 0..399 = 16x16 distance tiles, 256 threads (8,8,4).
// 400 blocks @ ~40KB smem -> ~2.7 resident blocks/SM (~22 warps/SM), breaking
// the 1-block/SM latency wall of the 100-block versions. Row-major smem
// (same layout as global): staging STS.128 consecutive-address ->
// conflict-free; stride-8 2x2 micro-tiles -> compute LDS conflict-free
// (A bank-pairs 4*ty distinct over warp, tx broadcast; B 4*tx distinct, ty
// broadcast). tz splits the 128 d-pairs into 4 slices; partials combined in
// fixed order -> deterministic. Subtract-form: exact, diag accumulates
// exactly +0 (reference row-max subtraction is a no-op there).
// Block 400 = exact rank sort + run bounds.
// ---------------------------------------------------------------------------
__global__ void __launch_bounds__(256)
fused_kernel(const float* __restrict__ F,
             const float* __restrict__ yt,
             const int* __restrict__ ye) {
    __shared__ float2 sA[TS * RSTRIDE];          // [16][130]
    __shared__ float2 sB[TS * RSTRIDE];          // negated B tile
    __shared__ float2 s_part[3 * 64 * 5];        // [(tz-1)*64+pos][5] (4 used)
    __shared__ float  s_y[NN];

    int tx = threadIdx.x, ty = threadIdx.y, tz = threadIdx.z;   // 8,8,4
    int tid = (tz * 8 + ty) * 8 + tx;
    int b = blockIdx.x;

    if (b == NTB) {
        // --- sort / bounds: O(N) exact counts per anchor ---
        for (int e = tid; e < NN; e += 256) s_y[e] = yt[e];
        __syncthreads();
        for (int e = tid; e < NN; e += 256) {
            float v = s_y[e];
            int rank = 0, gt = 0, geq = 0;
#pragma unroll 8
            for (int j = 0; j < NN; j++) {
                float w = s_y[j];
                float d = w - v;                       // same float expr as reference pld
                rank += (w < v) || (w == v && j < e);  // unique tie-broken rank
                gt  += !(d > 0.0f);
                geq += (d < 0.0f);
            }
            g_ys[rank] = v; g_perm[rank] = e; g_se[rank] = __ldg(&ye[e]);
            g_gt[e] = gt; g_geq[e] = geq;
        }
        return;
    }

    int bi = (b / 20) * TS, bj = (b % 20) * TS;

    // Stage A (as-is) and B (negated) row-major, FULL tile: 16 rows x 64
    // float4 = 1024 slots per tile; 256 threads x 4 iters.
#pragma unroll
    for (int v = 0; v < 4; v++) {
        int fidx = v * 256 + tid;     // 0..1023
        int row = fidx >> 6;          // 64 float4 per row
        int c4 = fidx & 63;
        float4 av = *(const float4*)(F + (bi + row) * DD + c4 * 4);
        float4 bv = *(const float4*)(F + (bj + row) * DD + c4 * 4);
        ((float4*)(sA + row * RSTRIDE))[c4] = av;
        ((float4*)(sB + row * RSTRIDE))[c4] = make_float4(-bv.x, -bv.y, -bv.z, -bv.w);
    }
    __syncthreads();

    // Slice tz covers dpairs [32tz, 32tz+32); micro-tile i = ty+8a, j = tx+8c.
    const float2* A0 = sA + (ty + 0) * RSTRIDE + tz * 32;
    const float2* A1 = sA + (ty + 8) * RSTRIDE + tz * 32;
    const float2* B0 = sB + (tx + 0) * RSTRIDE + tz * 32;
    const float2* B1 = sB + (tx + 8) * RSTRIDE + tz * 32;

    ull a00 = 0ull, a01 = 0ull, a10 = 0ull, a11 = 0ull;
#pragma unroll
    for (int q = 0; q < 32; q++) {
        ull x0 = *(const ull*)(A0 + q);
        ull x1 = *(const ull*)(A1 + q);
        ull y0 = *(const ull*)(B0 + q);
        ull y1 = *(const ull*)(B1 + q);
        dsq_acc(a00, x0, y0);
        dsq_acc(a01, x0, y1);
        dsq_acc(a10, x1, y0);
        dsq_acc(a11, x1, y1);
    }

    int pos = ty * 8 + tx;
    __syncthreads();                       // tiles no longer needed
    if (tz > 0) {
        float2* dst = s_part + ((tz - 1) * 64 + pos) * 5;
        dst[0] = *(float2*)&a00;
        dst[1] = *(float2*)&a01;
        dst[2] = *(float2*)&a10;
        dst[3] = *(float2*)&a11;
    }
    __syncthreads();
    if (tz == 0) {
        ull accs[4] = {a00, a01, a10, a11};
#pragma unroll
        for (int m = 0; m < 4; m++) {
            int a = m >> 1, c = m & 1;
            int i = ty + 8 * a, j = tx + 8 * c;
            float2 s = *(float2*)&accs[m];
            // fixed combine order over slices -> deterministic
#pragma unroll
            for (int sidx = 0; sidx < 3; sidx++) {
                float2 p = s_part[(sidx * 64 + pos) * 5 + m];
                s.x += p.x; s.y += p.y;
            }
            float d2 = s.x + s.y;          // >= 0 by construction; diag == +0
            float L = -0.5f * sqrtf(d2);
            g_L[(bi + i) * NN + (bj + j)] = L;
            g_E[(bi + i) * NN + (bj + j)] = __expf(L);
        }
    }
}

// ---------------------------------------------------------------------------
// Kernel 2: per-row class-split prefix sums (warp-shuffle scan). Block 0 also
// builds the global class-count prefix.
// ---------------------------------------------------------------------------
__global__ void scan_kernel() {
    __shared__ float ws0[10], ws1[10], wo0[10], wo1[10];
    __shared__ int   wsi[10], woi[10];
    int i = blockIdx.x, t = threadIdx.x;
    int lane = t & 31, w = t >> 5;

    int pj = g_perm[t];
    int cls = g_se[t];
    float Ev = (pj == i) ? 0.f : __ldg(&g_E[i * NN + pj]);   // eye mask folded
    float x0 = cls ? 0.f : Ev;
    float x1 = cls ? Ev : 0.f;
    int   xc = cls ? (1 << 10) : 1;

#pragma unroll
    for (int off = 1; off < 32; off <<= 1) {
        float a0 = __shfl_up_sync(0xffffffffu, x0, off);
        float a1 = __shfl_up_sync(0xffffffffu, x1, off);
        int   ac = __shfl_up_sync(0xffffffffu, xc, off);
        if (lane >= off) { x0 += a0; x1 += a1; xc += ac; }
    }
    if (lane == 31) { ws0[w] = x0; ws1[w] = x1; wsi[w] = xc; }
    __syncthreads();
    if (t == 0) {
        float r0 = 0.f, r1 = 0.f; int ri = 0;
#pragma unroll
        for (int q = 0; q < 10; q++) {
            wo0[q] = r0; wo1[q] = r1; woi[q] = ri;
            r0 += ws0[q]; r1 += ws1[q]; ri += wsi[q];
        }
    }
    __syncthreads();
    x0 += wo0[w]; x1 += wo1[w];
    float2* Prow = g_P + i * (NN + 1);
    Prow[t + 1] = make_float2(x0, x1);
    if (t == 0) Prow[0] = make_float2(0.f, 0.f);
    if (i == 0) {
        g_cnt[t + 1] = xc + woi[w];
        if (t == 0) g_cnt[0] = 0;
    }
}

// ---------------------------------------------------------------------------
// Kernel 3: block per anchor k, thread per row i. 2 binary searches + prefix
// assembly; exact integer-count validity; block reduce -> loss_k; last block
// (monotone counter modulo NN) produces the final scalar deterministically.
// ---------------------------------------------------------------------------
__global__ void lossk_kernel(const float* __restrict__ yt,
                             const int* __restrict__ ye,
                             float* __restrict__ out) {
    __shared__ float s_ys[NN];
    __shared__ int   s_cnt[NN + 1];
    __shared__ int   s_rb[7];
    __shared__ float rS[10], rC[10];
    __shared__ int   s_last;

    int k = blockIdx.x, t = threadIdx.x;
    int lane = t & 31, w = t >> 5;
    s_ys[t] = g_ys[t];
    s_cnt[t] = g_cnt[t];
    if (t == 0) s_cnt[NN] = g_cnt[NN];
    if (t < 7) s_rb[t] = c_rb[t];
    __syncthreads();

    float yk = __ldg(&yt[k]);
    int   ek = __ldg(&ye[k]);
    int   gt = g_gt[k], geq = g_geq[k];

    int i = t;
    float yi = yt[i];
    int   ei = ye[i];
    float pi = yi - yk;
    float a = fabsf(pi), na = -a;

    int base = ei + 10 * ek;
    int cid = (pi > 0.f) ? base : ((pi < 0.f) ? -base : 0);
    int cidx = (cid == -11) ? 0 : (cid == -10) ? 1 : (cid == -1) ? 2 :
               (cid == 0)   ? 3 : (cid == 1)   ? 4 : (cid == 10) ? 5 : 6;
    int rb = s_rb[cidx];

    // hi: first m with ys[m]-yk > a  (identical float expr as reference)
    int first = 0, count = NN;
    while (count > 0) {
        int half = count >> 1, mid = first + half;
        if (!(s_ys[mid] - yk > a)) { first = mid + 1; count -= half + 1; }
        else count = half;
    }
    int hi = first;
    // lo: first m with !(ys[m]-yk < -a)
    first = 0; count = NN;
    while (count > 0) {
        int half = count >> 1, mid = first + half;
        if (s_ys[mid] - yk < na) { first = mid + 1; count -= half + 1; }
        else count = half;
    }
    int lo = first;

    const float2* Prow = g_P + i * (NN + 1);
    float2 Pend = Prow[NN], Phi = Prow[hi], Plo = Prow[lo];
    float2 Pgt = Prow[gt], Pgq = Prow[geq];
    float SU0 = Pend.x - Phi.x, SU1 = Pend.y - Phi.y;
    float SL0 = Plo.x,          SL1 = Plo.y;
    float SM0 = (Phi.x - Plo.x) - (Pgt.x - Pgq.x);
    float SM1 = (Phi.y - Plo.y) - (Pgt.y - Pgq.y);

    float w10 = (float)((rb >> 2)  & 3), w20 = (float)((rb >> 4)  & 3), w30 = (float)((rb >> 6)  & 3);
    float w11 = (float)((rb >> 8)  & 3), w21 = (float)((rb >> 10) & 3), w31 = (float)((rb >> 12) & 3);
    float denom = 0.5f * (w10 * SL0 + w11 * SL1 + w20 * SM0 + w21 * SM1 + w30 * SU0 + w31 * SU1);

    // Exact integer validity: counts of positive-weight elements.
    int cU = s_cnt[NN] - s_cnt[hi];
    int cL = s_cnt[lo];
    int cM = (s_cnt[hi] - s_cnt[lo]) - (s_cnt[gt] - s_cnt[geq]);
    if (pi != 0.f) cM -= (ei ? (1 << 10) : 1);   // i sits in middle, weight 0 (eye)
    int nz = rb | (rb >> 1);
    int vsum = ((nz >> 2) & 1) * (cL & 1023) + ((nz >> 8)  & 1) * (cL >> 10)
             + ((nz >> 4) & 1) * (cM & 1023) + ((nz >> 10) & 1) * (cM >> 10)
             + ((nz >> 6) & 1) * (cU & 1023) + ((nz >> 12) & 1) * (cU >> 10);
    bool valid = (vsum > 0) && (i != k);

    float res = valid ? (__ldg(&g_L[k * NN + i]) - __logf(denom)) : 0.f;  // L symmetric
    float c   = valid ? 1.f : 0.f;

#pragma unroll
    for (int sh = 16; sh > 0; sh >>= 1) {
        res += __shfl_xor_sync(0xffffffffu, res, sh);
        c   += __shfl_xor_sync(0xffffffffu, c,   sh);
    }
    if (lane == 0) { rS[w] = res; rC[w] = c; }
    __syncthreads();
    if (t == 0) {
        float S = 0.f, C = 0.f;
#pragma unroll
        for (int q = 0; q < 10; q++) { S += rS[q]; C += rC[q]; }
        g_loss[k] = (C > 0.f) ? (-S / C) : 0.f;
        g_pos[k]  = (C > 0.f) ? 1.f : 0.f;
        __threadfence();
        int old = atomicAdd(&g_ctr, 1);
        s_last = ((old % NN) == NN - 1);   // monotone: no reset between replays
    }
    __syncthreads();
    if (s_last) {
        float sa = __ldcg(&g_loss[t]), sb = __ldcg(&g_pos[t]);
#pragma unroll
        for (int sh = 16; sh > 0; sh >>= 1) {
            sa += __shfl_xor_sync(0xffffffffu, sa, sh);
            sb += __shfl_xor_sync(0xffffffffu, sb, sh);
        }
        if (lane == 0) { rS[w] = sa; rC[w] = sb; }
        __syncthreads();
        if (t == 0) {
            float S = 0.f, P = 0.f;
#pragma unroll
            for (int q = 0; q < 10; q++) { S += rS[q]; P += rC[q]; }
            out[0] = S / P;
        }
    }
}

extern "C" void kernel_launch(void* const* d_in, const int* in_sizes, int n_in,
                              void* d_out, int out_size) {
    const float* features = (const float*)d_in[0];   // [320, 256] f32
    const float* y_times  = (const float*)d_in[1];   // [320] f32
    const int*   y_events = (const int*)d_in[2];     // [320] i32
    float* out = (float*)d_out;

    fused_kernel<<<NTB + 1, dim3(8, 8, 4)>>>(features, y_times, y_events);
    scan_kernel<<<NN, NN>>>();
    lossk_kernel<<<NN, NN>>>(y_times, y_events, out);
}

// round 12
// speedup vs baseline: 1.4410x; 1.1920x over previous
#include <cuda_runtime.h>
#include <cuda_bf16.h>

#define NN 320
#define DD 256
#define GB 320   // grid size; __launch_bounds__(320,3) guarantees >=3 blocks/SM
                 // -> 444 resident CTAs >= 320 -> spin barriers are safe

// Scratch (allocation-free device globals), 128B-aligned.
__device__ __align__(128) float  g_L[NN * NN];       // logits
__device__ __align__(128) float  g_E[NN * NN];       // exp(logits)
__device__ __align__(128) float  g_ys[NN];           // sorted y_times
__device__ __align__(128) int    g_perm[NN];         // sorted pos -> original idx
__device__ __align__(128) int    g_se[NN];           // event class, sorted order
__device__ __align__(128) int    g_gt[NN];           // per k: count !(ys-yk > 0)
__device__ __align__(128) int    g_geq[NN];          // per k: count (ys-yk < 0)
__device__ __align__(128) float2 g_P[NN * (NN + 1)]; // per-row class-split E prefix
__device__ __align__(128) int    g_cnt[NN + 32];     // class-count prefix (padded)
__device__ __align__(128) float  g_loss[NN];
__device__ __align__(128) float  g_pos[NN];
__device__ __align__(128) int    g_bar1;             // grid barrier 1 (monotone)
__device__ __align__(128) int    g_bar2;             // grid barrier 2 (monotone)
__device__ __align__(128) int    g_ctr;              // completion ctr (monotone)

// TABLE rows packed: weight code c in {0,1,2} (weight = c*0.5) at bits [2v+1:2v],
// v = td + 3*e, td in {1(lower),2(middle),3(upper)}.
__constant__ int c_rb[7] = {8852, 5460, 4692, 5460, 5716, 4436, 8852};

typedef unsigned long long ull;

// Packed fp32x2 helpers (sm_103a FFMA2 path). acc += (x + ny)^2 pairwise;
// x + (-y) is IEEE-identical to x - y.
__device__ __forceinline__ void dsq_acc(ull& acc, ull x, ull ny) {
    ull d;
    asm("add.rn.f32x2 %0, %1, %2;" : "=l"(d) : "l"(x), "l"(ny));
    asm("fma.rn.f32x2 %0, %1, %1, %0;" : "+l"(acc) : "l"(d));
}
__device__ __forceinline__ float dsum(ull acc) {
    unsigned lo, hi;
    asm("mov.b64 {%0, %1}, %2;" : "=r"(lo), "=r"(hi) : "l"(acc));
    return __uint_as_float(lo) + __uint_as_float(hi);
}

// Grid barrier: all GB blocks resident -> spin is safe. Monotone counter:
// epoch = old/GB, correct across graph replays with no reset.
__device__ __forceinline__ void grid_barrier(int* bar, int t) {
    __threadfence();
    __syncthreads();
    if (t == 0) {
        int old = atomicAdd(bar, 1);
        int target = (old / GB + 1) * GB;
        while (atomicAdd(bar, 0) < target) __nanosleep(64);
    }
    __syncthreads();
}

// ---------------------------------------------------------------------------
// ONE launch, three phases at their natural widths (the R10 mistake was
// striping phases A/B over 101 blocks; here grid = 320 so each phase maps
// 1:1 to blocks).
// Phase 0: blocks 0..99 = 32x32 distance tiles (R4-proven: d-major float2
//          smem, FFMA2 subtract-form, 2 K-stages; diag accumulates exactly
//          +0, matching the reference's no-op row-max). Block 100 = exact
//          rank sort + run bounds. Blocks 101..319 idle to the barrier.
// Phase A: block i computes row i's class-split E prefix sums.
// Phase B: block k computes loss_k; 320th finisher emits the final scalar.
// ---------------------------------------------------------------------------
__global__ void __launch_bounds__(320, 3)
mega_kernel(const float* __restrict__ F,
            const float* __restrict__ yt,
            const int* __restrict__ ye,
            float* __restrict__ out) {
    __shared__ float2 sA[64][33];   // d-major A tile (per 128-K stage)
    __shared__ float2 sB[64][33];   // negated B tile
    __shared__ float  s_y[NN];
    __shared__ float  ws0[10], ws1[10], wo0[10], wo1[10];
    __shared__ int    wsi[10], woi[10];
    __shared__ float  s_ys[NN];
    __shared__ int    s_cnt[NN + 1];
    __shared__ int    s_rb[7];
    __shared__ float  rS[10], rC[10];
    __shared__ int    s_last;

    int b = blockIdx.x;
    int t = threadIdx.x;          // 0..319
    int lane = t & 31, w = t >> 5;

    // ======================= Phase 0: distances + sort =====================
    if (b < 100) {
        bool act = (t < 256);
        int row = t >> 3;             // 0..31 (for t<256)
        int cg = (t & 7) << 4;        // 0,16,...,112 floats within 128-K stage
        int tx = t & 15, ty = (t >> 4) & 15;
        int bi = (b / 10) * 32, bj = (b % 10) * 32;
        ull a00 = 0ull, a01 = 0ull, a10 = 0ull, a11 = 0ull;

        for (int s = 0; s < 2; s++) {
            if (act) {
                const float* pA = F + (bi + row) * DD + s * 128 + cg;
                const float* pB = F + (bj + row) * DD + s * 128 + cg;
#pragma unroll
                for (int q = 0; q < 4; q++) {
                    float4 av = *(const float4*)(pA + 4 * q);
                    float4 bv = *(const float4*)(pB + 4 * q);
                    int dp = (cg + 4 * q) >> 1;
                    sA[dp][row]     = make_float2(av.x, av.y);
                    sA[dp + 1][row] = make_float2(av.z, av.w);
                    sB[dp][row]     = make_float2(-bv.x, -bv.y);
                    sB[dp + 1][row] = make_float2(-bv.z, -bv.w);
                }
            }
            __syncthreads();
            if (act) {
#pragma unroll 16
                for (int dd = 0; dd < 64; dd++) {
                    ull x0 = *(const ull*)&sA[dd][2 * ty];
                    ull x1 = *(const ull*)&sA[dd][2 * ty + 1];
                    ull y0 = *(const ull*)&sB[dd][2 * tx];
                    ull y1 = *(const ull*)&sB[dd][2 * tx + 1];
                    dsq_acc(a00, x0, y0);
                    dsq_acc(a01, x0, y1);
                    dsq_acc(a10, x1, y0);
                    dsq_acc(a11, x1, y1);
                }
            }
            __syncthreads();
        }
        if (act) {
            int i0 = bi + 2 * ty, j0 = bj + 2 * tx;
            float L;
            L = -0.5f * sqrtf(dsum(a00)); g_L[i0 * NN + j0]           = L; g_E[i0 * NN + j0]           = __expf(L);
            L = -0.5f * sqrtf(dsum(a01)); g_L[i0 * NN + j0 + 1]       = L; g_E[i0 * NN + j0 + 1]       = __expf(L);
            L = -0.5f * sqrtf(dsum(a10)); g_L[(i0 + 1) * NN + j0]     = L; g_E[(i0 + 1) * NN + j0]     = __expf(L);
            L = -0.5f * sqrtf(dsum(a11)); g_L[(i0 + 1) * NN + j0 + 1] = L; g_E[(i0 + 1) * NN + j0 + 1] = __expf(L);
        }
    } else if (b == 100) {   // exact rank sort + run bounds, one anchor/thread
        s_y[t] = yt[t];
        __syncthreads();
        {
            int e = t;
            float v = s_y[e];
            int rank = 0, gt = 0, geq = 0;
#pragma unroll 8
            for (int j = 0; j < NN; j++) {
                float wv = s_y[j];
                float d = wv - v;                        // same float expr as reference pld
                rank += (wv < v) || (wv == v && j < e);  // unique tie-broken rank
                gt  += !(d > 0.0f);
                geq += (d < 0.0f);
            }
            g_ys[rank] = v; g_perm[rank] = e; g_se[rank] = __ldg(&ye[e]);
            g_gt[e] = gt; g_geq[e] = geq;
        }
    }
    // blocks 101..319: straight to the barrier

    grid_barrier(&g_bar1, t);

    // ============ Phase A: class-split prefix sums, row i = b ==============
    {
        int i = b;
        int pj = g_perm[t];
        int cls = g_se[t];
        float Ev = (pj == i) ? 0.f : __ldcg(&g_E[i * NN + pj]);  // eye mask folded
        float x0 = cls ? 0.f : Ev;
        float x1 = cls ? Ev : 0.f;
        int   xc = cls ? (1 << 10) : 1;

#pragma unroll
        for (int off = 1; off < 32; off <<= 1) {
            float a0 = __shfl_up_sync(0xffffffffu, x0, off);
            float a1 = __shfl_up_sync(0xffffffffu, x1, off);
            int   ac = __shfl_up_sync(0xffffffffu, xc, off);
            if (lane >= off) { x0 += a0; x1 += a1; xc += ac; }
        }
        if (lane == 31) { ws0[w] = x0; ws1[w] = x1; wsi[w] = xc; }
        __syncthreads();
        if (t == 0) {
            float r0 = 0.f, r1 = 0.f; int ri = 0;
#pragma unroll
            for (int q = 0; q < 10; q++) {
                wo0[q] = r0; wo1[q] = r1; woi[q] = ri;
                r0 += ws0[q]; r1 += ws1[q]; ri += wsi[q];
            }
        }
        __syncthreads();
        x0 += wo0[w]; x1 += wo1[w];
        float2* Prow = g_P + i * (NN + 1);
        Prow[t + 1] = make_float2(x0, x1);
        if (t == 0) Prow[0] = make_float2(0.f, 0.f);
        if (i == 0) {
            g_cnt[t + 1] = xc + woi[w];
            if (t == 0) g_cnt[0] = 0;
        }
    }

    grid_barrier(&g_bar2, t);

    // ================ Phase B: per-anchor loss, k = b ======================
    s_ys[t] = g_ys[t];
    s_cnt[t] = __ldcg(&g_cnt[t]);
    if (t == 0) s_cnt[NN] = __ldcg(&g_cnt[NN]);
    if (t < 7) s_rb[t] = c_rb[t];
    __syncthreads();

    {
        int k = b;
        float yk = __ldg(&yt[k]);
        int   ek = __ldg(&ye[k]);
        int   gt = g_gt[k], geq = g_geq[k];

        int   i  = t;
        float yi = yt[i];
        int   ei = ye[i];
        float pi = yi - yk;
        float a = fabsf(pi), na = -a;

        int base = ei + 10 * ek;
        int cid = (pi > 0.f) ? base : ((pi < 0.f) ? -base : 0);
        int cidx = (cid == -11) ? 0 : (cid == -10) ? 1 : (cid == -1) ? 2 :
                   (cid == 0)   ? 3 : (cid == 1)   ? 4 : (cid == 10) ? 5 : 6;
        int rb = s_rb[cidx];

        // hi: first m with ys[m]-yk > a  (identical float expr as reference)
        int first = 0, count = NN;
        while (count > 0) {
            int half = count >> 1, mid = first + half;
            if (!(s_ys[mid] - yk > a)) { first = mid + 1; count -= half + 1; }
            else count = half;
        }
        int hi = first;
        // lo: first m with !(ys[m]-yk < -a)
        first = 0; count = NN;
        while (count > 0) {
            int half = count >> 1, mid = first + half;
            if (s_ys[mid] - yk < na) { first = mid + 1; count -= half + 1; }
            else count = half;
        }
        int lo = first;

        const float2* Prow = g_P + i * (NN + 1);
        float2 Pend = __ldcg(&Prow[NN]);
        float2 Phi  = __ldcg(&Prow[hi]);
        float2 Plo  = __ldcg(&Prow[lo]);
        float2 Pgt  = __ldcg(&Prow[gt]);
        float2 Pgq  = __ldcg(&Prow[geq]);
        float SU0 = Pend.x - Phi.x, SU1 = Pend.y - Phi.y;
        float SL0 = Plo.x,          SL1 = Plo.y;
        float SM0 = (Phi.x - Plo.x) - (Pgt.x - Pgq.x);
        float SM1 = (Phi.y - Plo.y) - (Pgt.y - Pgq.y);

        float w10 = (float)((rb >> 2)  & 3), w20 = (float)((rb >> 4)  & 3), w30 = (float)((rb >> 6)  & 3);
        float w11 = (float)((rb >> 8)  & 3), w21 = (float)((rb >> 10) & 3), w31 = (float)((rb >> 12) & 3);
        float denom = 0.5f * (w10 * SL0 + w11 * SL1 + w20 * SM0 + w21 * SM1 + w30 * SU0 + w31 * SU1);

        // Exact integer validity: counts of positive-weight elements.
        int cU = s_cnt[NN] - s_cnt[hi];
        int cL = s_cnt[lo];
        int cM = (s_cnt[hi] - s_cnt[lo]) - (s_cnt[gt] - s_cnt[geq]);
        if (pi != 0.f) cM -= (ei ? (1 << 10) : 1);   // i in middle, weight 0 (eye)
        int nz = rb | (rb >> 1);
        int vsum = ((nz >> 2) & 1) * (cL & 1023) + ((nz >> 8)  & 1) * (cL >> 10)
                 + ((nz >> 4) & 1) * (cM & 1023) + ((nz >> 10) & 1) * (cM >> 10)
                 + ((nz >> 6) & 1) * (cU & 1023) + ((nz >> 12) & 1) * (cU >> 10);
        bool valid = (vsum > 0) && (i != k);

        float res = valid ? (__ldcg(&g_L[k * NN + i]) - __logf(denom)) : 0.f;  // L symmetric
        float c   = valid ? 1.f : 0.f;

#pragma unroll
        for (int sh = 16; sh > 0; sh >>= 1) {
            res += __shfl_xor_sync(0xffffffffu, res, sh);
            c   += __shfl_xor_sync(0xffffffffu, c,   sh);
        }
        if (lane == 0) { rS[w] = res; rC[w] = c; }
        __syncthreads();
        if (t == 0) {
            float S = 0.f, C = 0.f;
#pragma unroll
            for (int q = 0; q < 10; q++) { S += rS[q]; C += rC[q]; }
            g_loss[k] = (C > 0.f) ? (-S / C) : 0.f;
            g_pos[k]  = (C > 0.f) ? 1.f : 0.f;
            __threadfence();
            int old = atomicAdd(&g_ctr, 1);
            s_last = ((old % NN) == NN - 1);   // monotone across replays
        }
        __syncthreads();
        if (s_last) {
            float sa = __ldcg(&g_loss[t]), sb = __ldcg(&g_pos[t]);
#pragma unroll
            for (int sh = 16; sh > 0; sh >>= 1) {
                sa += __shfl_xor_sync(0xffffffffu, sa, sh);
                sb += __shfl_xor_sync(0xffffffffu, sb, sh);
            }
            if (lane == 0) { rS[w] = sa; rC[w] = sb; }
            __syncthreads();
            if (t == 0) {
                float S = 0.f, P = 0.f;
#pragma unroll
                for (int q = 0; q < 10; q++) { S += rS[q]; P += rC[q]; }
                out[0] = S / P;
            }
        }
    }
}

extern "C" void kernel_launch(void* const* d_in, const int* in_sizes, int n_in,
                              void* d_out, int out_size) {
    const float* features = (const float*)d_in[0];   // [320, 256] f32
    const float* y_times  = (const float*)d_in[1];   // [320] f32
    const int*   y_events = (const int*)d_in[2];     // [320] i32
    float* out = (float*)d_out;

    mega_kernel<<<GB, 320>>>(features, y_times, y_events, out);
}

// round 13
// speedup vs baseline: 1.5452x; 1.0723x over previous
#include <cuda_runtime.h>
#include <cuda_bf16.h>

#define NN 320
#define DD 256
#define GB 320   // scanloss grid; __launch_bounds__(320,3) -> >=444 resident
                 // CTAs >= 320 -> spin barrier is deadlock-free

// Scratch (allocation-free device globals)
__device__ float  g_L[NN * NN];       // logits (bit-exact symmetric)
__device__ float  g_E[NN * NN];       // exp(logits)
__device__ float  g_ys[NN];           // sorted y_times
__device__ int    g_perm[NN];         // sorted pos -> original index
__device__ int    g_se[NN];           // event class in sorted order
__device__ int    g_gt[NN];           // per k: count of !(ys-yk > 0)
__device__ int    g_geq[NN];          // per k: count of (ys-yk < 0)
__device__ float2 g_P[NN * (NN + 1)]; // per-row class-split E prefix sums
__device__ int    g_cnt[NN + 1];      // class-count prefix, packed c1<<10 | c0
__device__ float  g_loss[NN];
__device__ float  g_pos[NN];
__device__ int    g_bar;              // grid barrier (monotone across replays)
__device__ int    g_ctr;              // lossk completion (monotone across replays)

// TABLE rows packed: weight code c in {0,1,2} (weight = c*0.5) at bits [2v+1:2v],
// v = td + 3*e, td in {1(lower),2(middle),3(upper)}.
__constant__ int c_rb[7] = {8852, 5460, 4692, 5460, 5716, 4436, 8852};

typedef unsigned long long ull;

// Packed fp32x2 helpers (sm_103a FFMA2 path — only reachable via PTX).
// acc += (x + ny)^2 elementwise; x + (-y) is IEEE-identical to x - y.
__device__ __forceinline__ void dsq_acc(ull& acc, ull x, ull ny) {
    ull d;
    asm("add.rn.f32x2 %0, %1, %2;" : "=l"(d) : "l"(x), "l"(ny));
    asm("fma.rn.f32x2 %0, %1, %1, %0;" : "+l"(acc) : "l"(d));
}
__device__ __forceinline__ float dsum(ull acc) {
    unsigned lo, hi;
    asm("mov.b64 {%0, %1}, %2;" : "=r"(lo), "=r"(hi) : "l"(acc));
    return __uint_as_float(lo) + __uint_as_float(hi);
}

// ---------------------------------------------------------------------------
// Kernel 1 (VERBATIM from the 23.0us/9.3e-8 build): distances (blocks 0..99,
// f32x2-packed 2x2 micro-tiles over 32x32 output tiles, K staged in 2 chunks)
// + exact rank sort / bounds (blocks 100,101). Row-max subtraction in the
// reference is a no-op (diag logit == 0 == row max); d = x + (-y) is
// IEEE-identical to x - y; (i,j)/(j,i) square negated diffs -> bit-exact
// symmetric L.
// ---------------------------------------------------------------------------
__global__ void dist_kernel(const float* __restrict__ F,
                            const float* __restrict__ yt,
                            const int* __restrict__ ye) {
    __shared__ float2 sA[64][33];   // [dpair][i], pad 33 kills STS conflicts
    __shared__ float2 sB[64][33];   // negated B tile
    __shared__ float  s_y[NN];
    int tx = threadIdx.x, ty = threadIdx.y;       // 16 x 16
    int tid = ty * 16 + tx;
    int b = blockIdx.x;

    if (b >= 100) {
        // --- sort / bounds block: 160 anchors each, O(N) exact counts ---
        for (int e = tid; e < NN; e += 256) s_y[e] = yt[e];
        __syncthreads();
        if (tid < 160) {
            int e = (b - 100) * 160 + tid;
            float v = s_y[e];
            int rank = 0, gt = 0, geq = 0;
#pragma unroll 8
            for (int j = 0; j < NN; j++) {
                float w = s_y[j];
                float d = w - v;                       // same float expr as reference pld
                rank += (w < v) || (w == v && j < e);  // unique tie-broken rank
                gt  += !(d > 0.0f);
                geq += (d < 0.0f);
            }
            g_ys[rank] = v; g_perm[rank] = e; g_se[rank] = __ldg(&ye[e]);
            g_gt[e] = gt; g_geq[e] = geq;
        }
        return;
    }

    int bi = (b / 10) * 32, bj = (b % 10) * 32;
    int row = tid >> 3;            // 0..31
    int col0 = (tid & 7) << 4;     // 0,16,...,112 (floats within 128-chunk)

    ull a00 = 0ull, a01 = 0ull, a10 = 0ull, a11 = 0ull;

    for (int s = 0; s < 2; s++) {
        const float* pA = F + (bi + row) * DD + s * 128 + col0;
        const float* pB = F + (bj + row) * DD + s * 128 + col0;
#pragma unroll
        for (int q = 0; q < 4; q++) {
            float4 av = *(const float4*)(pA + 4 * q);
            float4 bv = *(const float4*)(pB + 4 * q);
            int dp = (col0 + 4 * q) >> 1;
            sA[dp][row]     = make_float2(av.x, av.y);
            sA[dp + 1][row] = make_float2(av.z, av.w);
            sB[dp][row]     = make_float2(-bv.x, -bv.y);
            sB[dp + 1][row] = make_float2(-bv.z, -bv.w);
        }
        __syncthreads();
#pragma unroll 16
        for (int dd = 0; dd < 64; dd++) {
            ull x0 = *(const ull*)&sA[dd][2 * ty];
            ull x1 = *(const ull*)&sA[dd][2 * ty + 1];
            ull y0 = *(const ull*)&sB[dd][2 * tx];
            ull y1 = *(const ull*)&sB[dd][2 * tx + 1];
            dsq_acc(a00, x0, y0);
            dsq_acc(a01, x0, y1);
            dsq_acc(a10, x1, y0);
            dsq_acc(a11, x1, y1);
        }
        __syncthreads();
    }

    int i0 = bi + 2 * ty, j0 = bj + 2 * tx;
    float L;
    L = -0.5f * sqrtf(dsum(a00)); g_L[i0 * NN + j0]           = L; g_E[i0 * NN + j0]           = __expf(L);
    L = -0.5f * sqrtf(dsum(a01)); g_L[i0 * NN + j0 + 1]       = L; g_E[i0 * NN + j0 + 1]       = __expf(L);
    L = -0.5f * sqrtf(dsum(a10)); g_L[(i0 + 1) * NN + j0]     = L; g_E[(i0 + 1) * NN + j0]     = __expf(L);
    L = -0.5f * sqrtf(dsum(a11)); g_L[(i0 + 1) * NN + j0 + 1] = L; g_E[(i0 + 1) * NN + j0 + 1] = __expf(L);
}

// Grid barrier: all GB blocks resident (launch_bounds(320,3) -> >=444
// resident >= 320). Monotone counter: epoch = old/GB, correct across graph
// replays with no reset.
__device__ __forceinline__ void grid_barrier(int* bar, int t) {
    __threadfence();
    __syncthreads();
    if (t == 0) {
        int old = atomicAdd(bar, 1);
        int target = (old / GB + 1) * GB;
        while (atomicAdd(bar, 0) < target) __nanosleep(64);
    }
    __syncthreads();
}

// ---------------------------------------------------------------------------
// Kernel 2: scan + lossk fused, one grid barrier between them (saves one
// kernel launch overhead vs the 3-launch build). Both phases at their natural
// 320-wide shapes; arithmetic bit-identical to the 23.0us build.
// Phase A: block i = class-split E prefix sums of row i (warp-shuffle scan).
// Phase B: block k = per-anchor loss via 2 binary searches + prefix assembly;
//          exact integer-count validity; 320th finisher emits the scalar.
// ---------------------------------------------------------------------------
__global__ void __launch_bounds__(320, 3)
scanloss_kernel(const float* __restrict__ yt,
                const int* __restrict__ ye,
                float* __restrict__ out) {
    __shared__ float ws0[10], ws1[10], wo0[10], wo1[10];
    __shared__ int   wsi[10], woi[10];
    __shared__ float s_ys[NN];
    __shared__ int   s_cnt[NN + 1];
    __shared__ int   s_rb[7];
    __shared__ float rS[10], rC[10];
    __shared__ int   s_last;

    int b = blockIdx.x, t = threadIdx.x;
    int lane = t & 31, w = t >> 5;

    // ================= Phase A: scan, row i = b ===========================
    {
        int i = b;
        int pj = g_perm[t];
        int cls = g_se[t];
        float Ev = (pj == i) ? 0.f : __ldg(&g_E[i * NN + pj]);   // eye mask folded
        float x0 = cls ? 0.f : Ev;
        float x1 = cls ? Ev : 0.f;
        int   xc = cls ? (1 << 10) : 1;

#pragma unroll
        for (int off = 1; off < 32; off <<= 1) {
            float a0 = __shfl_up_sync(0xffffffffu, x0, off);
            float a1 = __shfl_up_sync(0xffffffffu, x1, off);
            int   ac = __shfl_up_sync(0xffffffffu, xc, off);
            if (lane >= off) { x0 += a0; x1 += a1; xc += ac; }
        }
        if (lane == 31) { ws0[w] = x0; ws1[w] = x1; wsi[w] = xc; }
        __syncthreads();
        if (t == 0) {
            float r0 = 0.f, r1 = 0.f; int ri = 0;
#pragma unroll
            for (int q = 0; q < 10; q++) {
                wo0[q] = r0; wo1[q] = r1; woi[q] = ri;
                r0 += ws0[q]; r1 += ws1[q]; ri += wsi[q];
            }
        }
        __syncthreads();
        x0 += wo0[w]; x1 += wo1[w];
        float2* Prow = g_P + i * (NN + 1);
        Prow[t + 1] = make_float2(x0, x1);
        if (t == 0) Prow[0] = make_float2(0.f, 0.f);
        if (i == 0) {
            g_cnt[t + 1] = xc + woi[w];
            if (t == 0) g_cnt[0] = 0;
        }
    }

    grid_barrier(&g_bar, t);

    // ================= Phase B: per-anchor loss, k = b =====================
    s_ys[t] = g_ys[t];
    s_cnt[t] = __ldcg(&g_cnt[t]);
    if (t == 0) s_cnt[NN] = __ldcg(&g_cnt[NN]);
    if (t < 7) s_rb[t] = c_rb[t];
    __syncthreads();

    {
        int k = b;
        float yk = __ldg(&yt[k]);
        int   ek = __ldg(&ye[k]);
        int   gt = g_gt[k], geq = g_geq[k];

        int   i  = t;
        float yi = yt[i];
        int   ei = ye[i];
        float pi = yi - yk;
        float a = fabsf(pi), na = -a;

        int base = ei + 10 * ek;
        int cid = (pi > 0.f) ? base : ((pi < 0.f) ? -base : 0);
        int cidx = (cid == -11) ? 0 : (cid == -10) ? 1 : (cid == -1) ? 2 :
                   (cid == 0)   ? 3 : (cid == 1)   ? 4 : (cid == 10) ? 5 : 6;
        int rb = s_rb[cidx];

        // hi: first m with ys[m]-yk > a  (identical float expr as reference)
        int first = 0, count = NN;
        while (count > 0) {
            int half = count >> 1, mid = first + half;
            if (!(s_ys[mid] - yk > a)) { first = mid + 1; count -= half + 1; }
            else count = half;
        }
        int hi = first;
        // lo: first m with !(ys[m]-yk < -a)
        first = 0; count = NN;
        while (count > 0) {
            int half = count >> 1, mid = first + half;
            if (s_ys[mid] - yk < na) { first = mid + 1; count -= half + 1; }
            else count = half;
        }
        int lo = first;

        // __ldcg: g_P written this launch by other SMs; bypass L1.
        const float2* Prow = g_P + i * (NN + 1);
        float2 Pend = __ldcg(&Prow[NN]);
        float2 Phi  = __ldcg(&Prow[hi]);
        float2 Plo  = __ldcg(&Prow[lo]);
        float2 Pgt  = __ldcg(&Prow[gt]);
        float2 Pgq  = __ldcg(&Prow[geq]);
        float SU0 = Pend.x - Phi.x, SU1 = Pend.y - Phi.y;
        float SL0 = Plo.x,          SL1 = Plo.y;
        float SM0 = (Phi.x - Plo.x) - (Pgt.x - Pgq.x);
        float SM1 = (Phi.y - Plo.y) - (Pgt.y - Pgq.y);

        float w10 = (float)((rb >> 2)  & 3), w20 = (float)((rb >> 4)  & 3), w30 = (float)((rb >> 6)  & 3);
        float w11 = (float)((rb >> 8)  & 3), w21 = (float)((rb >> 10) & 3), w31 = (float)((rb >> 12) & 3);
        float denom = 0.5f * (w10 * SL0 + w11 * SL1 + w20 * SM0 + w21 * SM1 + w30 * SU0 + w31 * SU1);

        // Exact integer validity: counts of positive-weight elements.
        int cU = s_cnt[NN] - s_cnt[hi];
        int cL = s_cnt[lo];
        int cM = (s_cnt[hi] - s_cnt[lo]) - (s_cnt[gt] - s_cnt[geq]);
        if (pi != 0.f) cM -= (ei ? (1 << 10) : 1);   // i sits in middle, weight 0 (eye)
        int nz = rb | (rb >> 1);
        int vsum = ((nz >> 2) & 1) * (cL & 1023) + ((nz >> 8)  & 1) * (cL >> 10)
                 + ((nz >> 4) & 1) * (cM & 1023) + ((nz >> 10) & 1) * (cM >> 10)
                 + ((nz >> 6) & 1) * (cU & 1023) + ((nz >> 12) & 1) * (cU >> 10);
        bool valid = (vsum > 0) && (i != k);

        float res = valid ? (__ldg(&g_L[k * NN + i]) - __logf(denom)) : 0.f;  // L symmetric
        float c   = valid ? 1.f : 0.f;

#pragma unroll
        for (int sh = 16; sh > 0; sh >>= 1) {
            res += __shfl_xor_sync(0xffffffffu, res, sh);
            c   += __shfl_xor_sync(0xffffffffu, c,   sh);
        }
        if (lane == 0) { rS[w] = res; rC[w] = c; }
        __syncthreads();
        if (t == 0) {
            float S = 0.f, C = 0.f;
#pragma unroll
            for (int q = 0; q < 10; q++) { S += rS[q]; C += rC[q]; }
            g_loss[k] = (C > 0.f) ? (-S / C) : 0.f;
            g_pos[k]  = (C > 0.f) ? 1.f : 0.f;
            __threadfence();
            int old = atomicAdd(&g_ctr, 1);
            s_last = ((old % NN) == NN - 1);   // monotone: no reset across replays
        }
        __syncthreads();
        if (s_last) {
            float sa = __ldcg(&g_loss[t]), sb = __ldcg(&g_pos[t]);
#pragma unroll
            for (int sh = 16; sh > 0; sh >>= 1) {
                sa += __shfl_xor_sync(0xffffffffu, sa, sh);
                sb += __shfl_xor_sync(0xffffffffu, sb, sh);
            }
            if (lane == 0) { rS[w] = sa; rC[w] = sb; }
            __syncthreads();
            if (t == 0) {
                float S = 0.f, P = 0.f;
#pragma unroll
                for (int q = 0; q < 10; q++) { S += rS[q]; P += rC[q]; }
                out[0] = S / P;
            }
        }
    }
}

extern "C" void kernel_launch(void* const* d_in, const int* in_sizes, int n_in,
                              void* d_out, int out_size) {
    const float* features = (const float*)d_in[0];   // [320, 256] f32
    const float* y_times  = (const float*)d_in[1];   // [320] f32
    const int*   y_events = (const int*)d_in[2];     // [320] i32
    float* out = (float*)d_out;

    dist_kernel<<<102, dim3(16, 16)>>>(features, y_times, y_events);
    scanloss_kernel<<<GB, 320>>>(y_times, y_events, out);
}